// round 2
// baseline (speedup 1.0000x reference)
#include <cuda_runtime.h>
#include <math.h>

#define Hh 128
#define CB 32
#define PAD 33
#define HS_L (Hh*PAD)
#define NTHREADS 256
#define NBLOCKS 128

// Output layout (concatenated return tuple, float32):
// decoder_output (4096,100,4) | dec_hidden (4,4096,128) | encoder_output (4096,64,128) | enc_hidden (4,4096,128) | loss (1)
#define DEC_OUT_OFF 0ul
#define DEC_HID_OFF 1638400ul
#define ENC_OUT_OFF 3735552ul
#define ENC_HID_OFF 37289984ul
#define LOSS_OFF    39387136ul

// Transposed weight scratch offsets (floats). Layout per matrix: [gate][k][j]
#define ENC_WIH0_T 0
#define ENC_WHH0_T 1536
#define ENC_WIH_T  50688
#define ENC_WHH_T  198144
#define DEC_WIH0_T 345600
#define DEC_WHH0_T 347136
#define DEC_WIH_T  396288
#define DEC_WHH_T  543744
#define LIN1_T     691200
#define WT_TOTAL   707584

__device__ float g_wt[WT_TOTAL];

// ---------------- prep kernels ----------------

// src: [3*H][K] row-major -> g_wt[dstOff + (g*K + k)*H + jj]
__global__ void k_tr_gates(const float* __restrict__ src, int dstOff, int K)
{
    int n = 3 * Hh * K;
    for (int idx = blockIdx.x * blockDim.x + threadIdx.x; idx < n;
         idx += gridDim.x * blockDim.x) {
        int jr = idx / K;
        int k  = idx - jr * K;
        int g  = jr >> 7;
        int jj = jr & (Hh - 1);
        g_wt[dstOff + (g * K + k) * Hh + jj] = src[idx];
    }
}

// lin1_w [H][H] -> g_wt[LIN1_T + k*H + i]
__global__ void k_tr_lin1(const float* __restrict__ src)
{
    int n = Hh * Hh;
    for (int idx = blockIdx.x * blockDim.x + threadIdx.x; idx < n;
         idx += gridDim.x * blockDim.x) {
        int i = idx >> 7;
        int k = idx & (Hh - 1);
        g_wt[LIN1_T + k * Hh + i] = src[idx];
    }
}

__global__ void k_zero_loss(float* __restrict__ out)
{
    if (threadIdx.x == 0) out[LOSS_OFF] = 0.0f;
}

// ---------------- main kernel ----------------

__device__ __forceinline__ float sigf(float x)
{
    return 1.0f / (1.0f + __expf(-x));
}

__device__ __forceinline__ float tanhfast(float x)
{
    float t = __expf(2.0f * x);
    return 1.0f - 2.0f / (t + 1.0f);   // safe at +/- inf
}

// One GRU layer for the block's 32-batch chunk.
// Thread mapping: warp w: j = (w&3)*32 + lane, b-range = (w>>2)*16 .. +16
// wx: [3][KX][H] transposed, wh: [3][H][H] transposed.
// xs: smem [KX][PAD], hsl: smem [H][PAD] (in/out)
template <int KX>
__device__ __forceinline__ void gru_layer(
    const float* __restrict__ wx, const float* __restrict__ wh,
    const float* __restrict__ bih, const float* __restrict__ bhh,
    const float* __restrict__ xs, float* __restrict__ hsl,
    int j, int bB)
{
    float ar[16], az[16], ain[16], ahn[16];
    {
        float br  = bih[j] + bhh[j];
        float bz  = bih[Hh + j] + bhh[Hh + j];
        float bi  = bih[2 * Hh + j];
        float bh2 = bhh[2 * Hh + j];
#pragma unroll
        for (int bb = 0; bb < 16; bb++) {
            ar[bb] = br; az[bb] = bz; ain[bb] = bi; ahn[bb] = bh2;
        }
    }
    const float* whr = wh + j;
    const float* whz = wh + Hh * Hh + j;
    const float* whn = wh + 2 * Hh * Hh + j;

    if (KX == Hh) {
        // fused x/h loop (layers 1..3)
        const float* wxr = wx + j;
        const float* wxz = wx + KX * Hh + j;
        const float* wxn = wx + 2 * KX * Hh + j;
#pragma unroll 2
        for (int k = 0; k < Hh; k++) {
            float wr = whr[k * Hh], wz = whz[k * Hh], wn = whn[k * Hh];
            float vr = wxr[k * Hh], vz = wxz[k * Hh], vn = wxn[k * Hh];
            const float* hrow = hsl + k * PAD + bB;
            const float* xrow = xs + k * PAD + bB;
#pragma unroll
            for (int bb = 0; bb < 16; bb++) {
                float hv = hrow[bb];
                float xv = xrow[bb];
                ar[bb]  = fmaf(hv, wr, ar[bb]);
                az[bb]  = fmaf(hv, wz, az[bb]);
                ahn[bb] = fmaf(hv, wn, ahn[bb]);
                ar[bb]  = fmaf(xv, vr, ar[bb]);
                az[bb]  = fmaf(xv, vz, az[bb]);
                ain[bb] = fmaf(xv, vn, ain[bb]);
            }
        }
    } else {
        // h part
#pragma unroll 2
        for (int k = 0; k < Hh; k++) {
            float wr = whr[k * Hh], wz = whz[k * Hh], wn = whn[k * Hh];
            const float* hrow = hsl + k * PAD + bB;
#pragma unroll
            for (int bb = 0; bb < 16; bb++) {
                float hv = hrow[bb];
                ar[bb]  = fmaf(hv, wr, ar[bb]);
                az[bb]  = fmaf(hv, wz, az[bb]);
                ahn[bb] = fmaf(hv, wn, ahn[bb]);
            }
        }
        // x part (KX small)
        const float* wxr = wx + j;
        const float* wxz = wx + KX * Hh + j;
        const float* wxn = wx + 2 * KX * Hh + j;
#pragma unroll
        for (int k = 0; k < KX; k++) {
            float vr = wxr[k * Hh], vz = wxz[k * Hh], vn = wxn[k * Hh];
            const float* xrow = xs + k * PAD + bB;
#pragma unroll
            for (int bb = 0; bb < 16; bb++) {
                float xv = xrow[bb];
                ar[bb]  = fmaf(xv, vr, ar[bb]);
                az[bb]  = fmaf(xv, vz, az[bb]);
                ain[bb] = fmaf(xv, vn, ain[bb]);
            }
        }
    }
    __syncthreads();   // all reads of hsl done before overwrite
    float* hrow0 = hsl + j * PAD + bB;
#pragma unroll
    for (int bb = 0; bb < 16; bb++) {
        float hold = hrow0[bb];
        float r = sigf(ar[bb]);
        float z = sigf(az[bb]);
        float n = tanhfast(fmaf(r, ahn[bb], ain[bb]));
        hrow0[bb] = fmaf(z, hold - n, n);   // (1-z)*n + z*hold
    }
    __syncthreads();   // hsl ready for next layer
}

__global__ void __launch_bounds__(NTHREADS, 1) gru_main(
    const float* __restrict__ inp, const float* __restrict__ tgt,
    const float* __restrict__ enc_bih, const float* __restrict__ enc_bhh,
    const float* __restrict__ dec_bih, const float* __restrict__ dec_bhh,
    const float* __restrict__ lin1_b, const float* __restrict__ lin2_w,
    const float* __restrict__ lin2_b,
    float* __restrict__ out)
{
    extern __shared__ float sm[];
    float* hs  = sm;                        // [4][H][PAD]
    float* o1s = sm + 4 * HS_L;             // [H][PAD]
    float* x0s = o1s + HS_L;                // [4][PAD]
    float* red = x0s + 4 * PAD;             // [NTHREADS]

    const int tid  = threadIdx.x;
    const int lane = tid & 31;
    const int w    = tid >> 5;
    const int j    = ((w & 3) << 5) | lane;
    const int bB   = (w >> 2) << 4;
    const int b0   = blockIdx.x * CB;

    for (int u = tid; u < 4 * HS_L; u += NTHREADS) hs[u] = 0.0f;
    if (tid < CB * 4) {
        int b = tid >> 2, e = tid & 3;
        out[DEC_OUT_OFF + (size_t)(b0 + b) * 400 + e] =
            inp[(size_t)(b0 + b) * 256 + e];
    }
    __syncthreads();

    // ---------------- encoder: 64 steps ----------------
    for (int t = 0; t < 64; t++) {
        if (tid < CB * 4) {
            int b = tid >> 2, e = tid & 3;
            x0s[e * PAD + b] = inp[(size_t)(b0 + b) * 256 + t * 4 + e];
        }
        __syncthreads();
        gru_layer<4>(g_wt + ENC_WIH0_T, g_wt + ENC_WHH0_T,
                     enc_bih, enc_bhh, x0s, hs, j, bB);
#pragma unroll 1
        for (int l = 1; l < 4; l++) {
            gru_layer<Hh>(g_wt + ENC_WIH_T + (l - 1) * 3 * Hh * Hh,
                          g_wt + ENC_WHH_T + (l - 1) * 3 * Hh * Hh,
                          enc_bih + l * 384, enc_bhh + l * 384,
                          hs + (l - 1) * HS_L, hs + l * HS_L, j, bB);
        }
        const float* h3 = hs + 3 * HS_L;
        for (int u = tid; u < CB * Hh; u += NTHREADS) {
            int b = u >> 7, k = u & 127;
            out[ENC_OUT_OFF + (size_t)(b0 + b) * 8192 + t * 128 + k] =
                h3[k * PAD + b];
        }
        __syncthreads();
    }
    // enc_hidden (L,B,H)
    for (int u = tid; u < 4 * CB * Hh; u += NTHREADS) {
        int l = u >> 12, r = u & 4095, b = r >> 7, k = r & 127;
        out[ENC_HID_OFF + (size_t)l * 524288 + (size_t)(b0 + b) * 128 + k] =
            hs[l * HS_L + k * PAD + b];
    }

    // ---------------- decoder: 99 steps ----------------
    float lossAcc = 0.0f;
    for (int s = 0; s < 99; s++) {
        if (tid < CB * 4) {
            int b = tid >> 2, e = tid & 3;
            float xv = (s == 0) ? inp[(size_t)(b0 + b) * 256 + e]
                                : tgt[(size_t)(b0 + b) * 400 + s * 4 + e];
            x0s[e * PAD + b] = xv;
        }
        __syncthreads();
        gru_layer<4>(g_wt + DEC_WIH0_T, g_wt + DEC_WHH0_T,
                     dec_bih, dec_bhh, x0s, hs, j, bB);
#pragma unroll 1
        for (int l = 1; l < 4; l++) {
            gru_layer<Hh>(g_wt + DEC_WIH_T + (l - 1) * 3 * Hh * Hh,
                          g_wt + DEC_WHH_T + (l - 1) * 3 * Hh * Hh,
                          dec_bih + l * 384, dec_bhh + l * 384,
                          hs + (l - 1) * HS_L, hs + l * HS_L, j, bB);
        }
        // lin1 + relu -> o1s
        {
            float acc[16];
            float bi = lin1_b[j];
#pragma unroll
            for (int bb = 0; bb < 16; bb++) acc[bb] = bi;
            const float* top = hs + 3 * HS_L;
            const float* wt1 = g_wt + LIN1_T + j;
#pragma unroll 2
            for (int k = 0; k < Hh; k++) {
                float wv = wt1[k * Hh];
                const float* trow = top + k * PAD + bB;
#pragma unroll
                for (int bb = 0; bb < 16; bb++)
                    acc[bb] = fmaf(trow[bb], wv, acc[bb]);
            }
#pragma unroll
            for (int bb = 0; bb < 16; bb++)
                o1s[j * PAD + bB + bb] = fmaxf(acc[bb], 0.0f);
        }
        __syncthreads();
        // lin2 + loss + store
        if (tid < CB * 4) {
            int b = tid >> 2, e = tid & 3;
            float acc = lin2_b[e];
#pragma unroll 4
            for (int i = 0; i < Hh; i++)
                acc = fmaf(o1s[i * PAD + b], lin2_w[e * Hh + i], acc);
            float y = tgt[(size_t)(b0 + b) * 400 + (s + 1) * 4 + e];
            float d = acc - y;
            lossAcc += d * d;
            out[DEC_OUT_OFF + (size_t)(b0 + b) * 400 + (s + 1) * 4 + e] = acc;
        }
        __syncthreads();
    }
    // dec_hidden (L,B,H)
    for (int u = tid; u < 4 * CB * Hh; u += NTHREADS) {
        int l = u >> 12, r = u & 4095, b = r >> 7, k = r & 127;
        out[DEC_HID_OFF + (size_t)l * 524288 + (size_t)(b0 + b) * 128 + k] =
            hs[l * HS_L + k * PAD + b];
    }

    // loss reduction
    red[tid] = lossAcc;
    __syncthreads();
    for (int s2 = NTHREADS / 2; s2 > 0; s2 >>= 1) {
        if (tid < s2) red[tid] += red[tid + s2];
        __syncthreads();
    }
    if (tid == 0) atomicAdd(out + LOSS_OFF, red[0] * (1.0f / 16384.0f));
}

// ---------------- launch ----------------

extern "C" void kernel_launch(void* const* d_in, const int* in_sizes, int n_in,
                              void* d_out, int out_size)
{
    const float* inp      = (const float*)d_in[0];
    const float* tgt      = (const float*)d_in[1];
    const float* enc_wih0 = (const float*)d_in[2];
    const float* enc_whh0 = (const float*)d_in[3];
    const float* enc_wih  = (const float*)d_in[4];
    const float* enc_whh  = (const float*)d_in[5];
    const float* enc_bih  = (const float*)d_in[6];
    const float* enc_bhh  = (const float*)d_in[7];
    const float* dec_wih0 = (const float*)d_in[8];
    const float* dec_whh0 = (const float*)d_in[9];
    const float* dec_wih  = (const float*)d_in[10];
    const float* dec_whh  = (const float*)d_in[11];
    const float* dec_bih  = (const float*)d_in[12];
    const float* dec_bhh  = (const float*)d_in[13];
    const float* lin1_w   = (const float*)d_in[14];
    const float* lin1_b   = (const float*)d_in[15];
    const float* lin2_w   = (const float*)d_in[16];
    const float* lin2_b   = (const float*)d_in[17];
    float* out = (float*)d_out;

    const int smemBytes = (4 * HS_L + HS_L + 4 * PAD + NTHREADS) * 4;  // 86032
    cudaFuncSetAttribute(gru_main, cudaFuncAttributeMaxDynamicSharedMemorySize,
                         smemBytes);

    k_zero_loss<<<1, 32>>>(out);

    k_tr_gates<<<48, 256>>>(enc_wih0, ENC_WIH0_T, 4);
    k_tr_gates<<<48, 256>>>(enc_whh0, ENC_WHH0_T, 128);
    for (int l = 0; l < 3; l++) {
        k_tr_gates<<<48, 256>>>(enc_wih + l * 49152, ENC_WIH_T + l * 49152, 128);
        k_tr_gates<<<48, 256>>>(enc_whh + l * 49152, ENC_WHH_T + l * 49152, 128);
    }
    k_tr_gates<<<48, 256>>>(dec_wih0, DEC_WIH0_T, 4);
    k_tr_gates<<<48, 256>>>(dec_whh0, DEC_WHH0_T, 128);
    for (int l = 0; l < 3; l++) {
        k_tr_gates<<<48, 256>>>(dec_wih + l * 49152, DEC_WIH_T + l * 49152, 128);
        k_tr_gates<<<48, 256>>>(dec_whh + l * 49152, DEC_WHH_T + l * 49152, 128);
    }
    k_tr_lin1<<<48, 256>>>(lin1_w);

    gru_main<<<NBLOCKS, NTHREADS, smemBytes>>>(
        inp, tgt, enc_bih, enc_bhh, dec_bih, dec_bhh,
        lin1_b, lin2_w, lin2_b, out);
}

// round 3
// speedup vs baseline: 1.0698x; 1.0698x over previous
#include <cuda_runtime.h>
#include <math.h>

#define Hh 128
#define CB 32
#define PAD 34
#define HS_L (Hh*PAD)
#define NTHREADS 256
#define NBLOCKS 128

// Output layout (concatenated return tuple, float32):
// decoder_output (4096,100,4) | dec_hidden (4,4096,128) | encoder_output (4096,64,128) | enc_hidden (4,4096,128) | loss (1)
#define DEC_OUT_OFF 0ul
#define DEC_HID_OFF 1638400ul
#define ENC_OUT_OFF 3735552ul
#define ENC_HID_OFF 37289984ul
#define LOSS_OFF    39387136ul

// Transposed weight scratch offsets (floats). Layout per matrix: [gate][k][j]
#define ENC_WIH0_T 0
#define ENC_WHH0_T 1536
#define ENC_WIH_T  50688
#define ENC_WHH_T  198144
#define DEC_WIH0_T 345600
#define DEC_WHH0_T 347136
#define DEC_WIH_T  396288
#define DEC_WHH_T  543744
#define LIN1_T     691200
#define WT_TOTAL   707584

__device__ float g_wt[WT_TOTAL];

// ---------------- packed f32x2 helpers ----------------

typedef unsigned long long u64;

__device__ __forceinline__ u64 pack2s(float v)
{
    u64 r;
    asm("mov.b64 %0,{%1,%1};" : "=l"(r) : "f"(v));
    return r;
}
__device__ __forceinline__ void unpack2(u64 v, float& lo, float& hi)
{
    asm("mov.b64 {%0,%1},%2;" : "=f"(lo), "=f"(hi) : "l"(v));
}
__device__ __forceinline__ void ffma2(u64& d, u64 a, u64 b)
{
    asm("fma.rn.f32x2 %0,%1,%2,%3;" : "=l"(d) : "l"(a), "l"(b), "l"(d));
}

// ---------------- prep kernels ----------------

// src: [3*H][K] row-major -> g_wt[dstOff + (g*K + k)*H + jj]
__global__ void k_tr_gates(const float* __restrict__ src, int dstOff, int K)
{
    int n = 3 * Hh * K;
    for (int idx = blockIdx.x * blockDim.x + threadIdx.x; idx < n;
         idx += gridDim.x * blockDim.x) {
        int jr = idx / K;
        int k  = idx - jr * K;
        int g  = jr >> 7;
        int jj = jr & (Hh - 1);
        g_wt[dstOff + (g * K + k) * Hh + jj] = src[idx];
    }
}

// lin1_w [H][H] -> g_wt[LIN1_T + k*H + i]
__global__ void k_tr_lin1(const float* __restrict__ src)
{
    int n = Hh * Hh;
    for (int idx = blockIdx.x * blockDim.x + threadIdx.x; idx < n;
         idx += gridDim.x * blockDim.x) {
        int i = idx >> 7;
        int k = idx & (Hh - 1);
        g_wt[LIN1_T + k * Hh + i] = src[idx];
    }
}

__global__ void k_zero_loss(float* __restrict__ out)
{
    if (threadIdx.x == 0) out[LOSS_OFF] = 0.0f;
}

// ---------------- main kernel ----------------

__device__ __forceinline__ float sigf(float x)
{
    return 1.0f / (1.0f + __expf(-x));
}

__device__ __forceinline__ float tanhfast(float x)
{
    float t = __expf(2.0f * x);
    return 1.0f - 2.0f / (t + 1.0f);   // safe at +/- inf
}

// One GRU layer for the block's 32-batch chunk.
// Thread mapping: warp w: j = (w&3)*32 + lane, b-range = (w>>2)*16 .. +16
// wx: [3][KX][H] transposed, wh: [3][H][H] transposed.
// xs: smem [KX][PAD], hsl: smem [H][PAD] (in/out). All rows 8B-aligned.
template <int KX>
__device__ __forceinline__ void gru_layer(
    const float* __restrict__ wx, const float* __restrict__ wh,
    const float* __restrict__ bih, const float* __restrict__ bhh,
    const float* __restrict__ xs, float* __restrict__ hsl,
    int j, int bB)
{
    u64 ar[8], az[8], ain[8], ahn[8];
    {
        u64 br  = pack2s(bih[j] + bhh[j]);
        u64 bz  = pack2s(bih[Hh + j] + bhh[Hh + j]);
        u64 bi  = pack2s(bih[2 * Hh + j]);
        u64 bh2 = pack2s(bhh[2 * Hh + j]);
#pragma unroll
        for (int p = 0; p < 8; p++) {
            ar[p] = br; az[p] = bz; ain[p] = bi; ahn[p] = bh2;
        }
    }
    const float* whr = wh + j;
    const float* whz = wh + Hh * Hh + j;
    const float* whn = wh + 2 * Hh * Hh + j;

    if (KX == Hh) {
        // fused x/h loop (layers 1..3)
        const float* wxr = wx + j;
        const float* wxz = wx + KX * Hh + j;
        const float* wxn = wx + 2 * KX * Hh + j;
#pragma unroll 2
        for (int k = 0; k < Hh; k++) {
            u64 wr = pack2s(whr[k * Hh]);
            u64 wz = pack2s(whz[k * Hh]);
            u64 wn = pack2s(whn[k * Hh]);
            u64 vr = pack2s(wxr[k * Hh]);
            u64 vz = pack2s(wxz[k * Hh]);
            u64 vn = pack2s(wxn[k * Hh]);
            const u64* hrow = (const u64*)(hsl + k * PAD + bB);
            const u64* xrow = (const u64*)(xs + k * PAD + bB);
#pragma unroll
            for (int p = 0; p < 8; p++) {
                u64 hv = hrow[p];
                u64 xv = xrow[p];
                ffma2(ar[p], hv, wr);
                ffma2(az[p], hv, wz);
                ffma2(ahn[p], hv, wn);
                ffma2(ar[p], xv, vr);
                ffma2(az[p], xv, vz);
                ffma2(ain[p], xv, vn);
            }
        }
    } else {
        // h part
#pragma unroll 2
        for (int k = 0; k < Hh; k++) {
            u64 wr = pack2s(whr[k * Hh]);
            u64 wz = pack2s(whz[k * Hh]);
            u64 wn = pack2s(whn[k * Hh]);
            const u64* hrow = (const u64*)(hsl + k * PAD + bB);
#pragma unroll
            for (int p = 0; p < 8; p++) {
                u64 hv = hrow[p];
                ffma2(ar[p], hv, wr);
                ffma2(az[p], hv, wz);
                ffma2(ahn[p], hv, wn);
            }
        }
        // x part (KX small)
        const float* wxr = wx + j;
        const float* wxz = wx + KX * Hh + j;
        const float* wxn = wx + 2 * KX * Hh + j;
#pragma unroll
        for (int k = 0; k < KX; k++) {
            u64 vr = pack2s(wxr[k * Hh]);
            u64 vz = pack2s(wxz[k * Hh]);
            u64 vn = pack2s(wxn[k * Hh]);
            const u64* xrow = (const u64*)(xs + k * PAD + bB);
#pragma unroll
            for (int p = 0; p < 8; p++) {
                u64 xv = xrow[p];
                ffma2(ar[p], xv, vr);
                ffma2(az[p], xv, vz);
                ffma2(ain[p], xv, vn);
            }
        }
    }
    __syncthreads();   // all reads of hsl done before overwrite
    float* hrow0 = hsl + j * PAD + bB;
#pragma unroll
    for (int p = 0; p < 8; p++) {
        float r0, r1, z0, z1, i0, i1, n0, n1, h0, h1;
        unpack2(ar[p], r0, r1);
        unpack2(az[p], z0, z1);
        unpack2(ain[p], i0, i1);
        unpack2(ahn[p], n0, n1);
        h0 = hrow0[2 * p];
        h1 = hrow0[2 * p + 1];
        float rr0 = sigf(r0), rr1 = sigf(r1);
        float zz0 = sigf(z0), zz1 = sigf(z1);
        float nn0 = tanhfast(fmaf(rr0, n0, i0));
        float nn1 = tanhfast(fmaf(rr1, n1, i1));
        hrow0[2 * p]     = fmaf(zz0, h0 - nn0, nn0);
        hrow0[2 * p + 1] = fmaf(zz1, h1 - nn1, nn1);
    }
    __syncthreads();   // hsl ready for next layer
}

__global__ void __launch_bounds__(NTHREADS, 1) gru_main(
    const float* __restrict__ inp, const float* __restrict__ tgt,
    const float* __restrict__ enc_bih, const float* __restrict__ enc_bhh,
    const float* __restrict__ dec_bih, const float* __restrict__ dec_bhh,
    const float* __restrict__ lin1_b, const float* __restrict__ lin2_w,
    const float* __restrict__ lin2_b,
    float* __restrict__ out)
{
    extern __shared__ float sm[];
    float* hs  = sm;                        // [4][H][PAD]
    float* o1s = sm + 4 * HS_L;             // [H][PAD]
    float* x0s = o1s + HS_L;                // [4][PAD]
    float* red = x0s + 4 * PAD;             // [NTHREADS]

    const int tid  = threadIdx.x;
    const int lane = tid & 31;
    const int w    = tid >> 5;
    const int j    = ((w & 3) << 5) | lane;
    const int bB   = (w >> 2) << 4;
    const int b0   = blockIdx.x * CB;

    for (int u = tid; u < 4 * HS_L; u += NTHREADS) hs[u] = 0.0f;
    if (tid < CB * 4) {
        int b = tid >> 2, e = tid & 3;
        out[DEC_OUT_OFF + (size_t)(b0 + b) * 400 + e] =
            inp[(size_t)(b0 + b) * 256 + e];
    }
    __syncthreads();

    // ---------------- encoder: 64 steps ----------------
    for (int t = 0; t < 64; t++) {
        if (tid < CB * 4) {
            int b = tid >> 2, e = tid & 3;
            x0s[e * PAD + b] = inp[(size_t)(b0 + b) * 256 + t * 4 + e];
        }
        __syncthreads();
        gru_layer<4>(g_wt + ENC_WIH0_T, g_wt + ENC_WHH0_T,
                     enc_bih, enc_bhh, x0s, hs, j, bB);
#pragma unroll 1
        for (int l = 1; l < 4; l++) {
            gru_layer<Hh>(g_wt + ENC_WIH_T + (l - 1) * 3 * Hh * Hh,
                          g_wt + ENC_WHH_T + (l - 1) * 3 * Hh * Hh,
                          enc_bih + l * 384, enc_bhh + l * 384,
                          hs + (l - 1) * HS_L, hs + l * HS_L, j, bB);
        }
        const float* h3 = hs + 3 * HS_L;
        for (int u = tid; u < CB * Hh; u += NTHREADS) {
            int b = u >> 7, k = u & 127;
            out[ENC_OUT_OFF + (size_t)(b0 + b) * 8192 + t * 128 + k] =
                h3[k * PAD + b];
        }
        __syncthreads();
    }
    // enc_hidden (L,B,H)
    for (int u = tid; u < 4 * CB * Hh; u += NTHREADS) {
        int l = u >> 12, r = u & 4095, b = r >> 7, k = r & 127;
        out[ENC_HID_OFF + (size_t)l * 524288 + (size_t)(b0 + b) * 128 + k] =
            hs[l * HS_L + k * PAD + b];
    }

    // ---------------- decoder: 99 steps ----------------
    float lossAcc = 0.0f;
    for (int s = 0; s < 99; s++) {
        if (tid < CB * 4) {
            int b = tid >> 2, e = tid & 3;
            float xv = (s == 0) ? inp[(size_t)(b0 + b) * 256 + e]
                                : tgt[(size_t)(b0 + b) * 400 + s * 4 + e];
            x0s[e * PAD + b] = xv;
        }
        __syncthreads();
        gru_layer<4>(g_wt + DEC_WIH0_T, g_wt + DEC_WHH0_T,
                     dec_bih, dec_bhh, x0s, hs, j, bB);
#pragma unroll 1
        for (int l = 1; l < 4; l++) {
            gru_layer<Hh>(g_wt + DEC_WIH_T + (l - 1) * 3 * Hh * Hh,
                          g_wt + DEC_WHH_T + (l - 1) * 3 * Hh * Hh,
                          dec_bih + l * 384, dec_bhh + l * 384,
                          hs + (l - 1) * HS_L, hs + l * HS_L, j, bB);
        }
        // lin1 + relu -> o1s
        {
            u64 acc[8];
            u64 bi = pack2s(lin1_b[j]);
#pragma unroll
            for (int p = 0; p < 8; p++) acc[p] = bi;
            const float* top = hs + 3 * HS_L;
            const float* wt1 = g_wt + LIN1_T + j;
#pragma unroll 2
            for (int k = 0; k < Hh; k++) {
                u64 wv = pack2s(wt1[k * Hh]);
                const u64* trow = (const u64*)(top + k * PAD + bB);
#pragma unroll
                for (int p = 0; p < 8; p++)
                    ffma2(acc[p], trow[p], wv);
            }
            float* orow = o1s + j * PAD + bB;
#pragma unroll
            for (int p = 0; p < 8; p++) {
                float a0, a1;
                unpack2(acc[p], a0, a1);
                orow[2 * p]     = fmaxf(a0, 0.0f);
                orow[2 * p + 1] = fmaxf(a1, 0.0f);
            }
        }
        __syncthreads();
        // lin2 + loss + store
        if (tid < CB * 4) {
            int b = tid >> 2, e = tid & 3;
            float acc = lin2_b[e];
#pragma unroll 4
            for (int i = 0; i < Hh; i++)
                acc = fmaf(o1s[i * PAD + b], lin2_w[e * Hh + i], acc);
            float y = tgt[(size_t)(b0 + b) * 400 + (s + 1) * 4 + e];
            float d = acc - y;
            lossAcc += d * d;
            out[DEC_OUT_OFF + (size_t)(b0 + b) * 400 + (s + 1) * 4 + e] = acc;
        }
        __syncthreads();
    }
    // dec_hidden (L,B,H)
    for (int u = tid; u < 4 * CB * Hh; u += NTHREADS) {
        int l = u >> 12, r = u & 4095, b = r >> 7, k = r & 127;
        out[DEC_HID_OFF + (size_t)l * 524288 + (size_t)(b0 + b) * 128 + k] =
            hs[l * HS_L + k * PAD + b];
    }

    // loss reduction
    red[tid] = lossAcc;
    __syncthreads();
    for (int s2 = NTHREADS / 2; s2 > 0; s2 >>= 1) {
        if (tid < s2) red[tid] += red[tid + s2];
        __syncthreads();
    }
    if (tid == 0) atomicAdd(out + LOSS_OFF, red[0] * (1.0f / 16384.0f));
}

// ---------------- launch ----------------

extern "C" void kernel_launch(void* const* d_in, const int* in_sizes, int n_in,
                              void* d_out, int out_size)
{
    const float* inp      = (const float*)d_in[0];
    const float* tgt      = (const float*)d_in[1];
    const float* enc_wih0 = (const float*)d_in[2];
    const float* enc_whh0 = (const float*)d_in[3];
    const float* enc_wih  = (const float*)d_in[4];
    const float* enc_whh  = (const float*)d_in[5];
    const float* enc_bih  = (const float*)d_in[6];
    const float* enc_bhh  = (const float*)d_in[7];
    const float* dec_wih0 = (const float*)d_in[8];
    const float* dec_whh0 = (const float*)d_in[9];
    const float* dec_wih  = (const float*)d_in[10];
    const float* dec_whh  = (const float*)d_in[11];
    const float* dec_bih  = (const float*)d_in[12];
    const float* dec_bhh  = (const float*)d_in[13];
    const float* lin1_w   = (const float*)d_in[14];
    const float* lin1_b   = (const float*)d_in[15];
    const float* lin2_w   = (const float*)d_in[16];
    const float* lin2_b   = (const float*)d_in[17];
    float* out = (float*)d_out;

    const int smemBytes = (4 * HS_L + HS_L + 4 * PAD + NTHREADS) * 4;
    cudaFuncSetAttribute(gru_main, cudaFuncAttributeMaxDynamicSharedMemorySize,
                         smemBytes);

    k_zero_loss<<<1, 32>>>(out);

    k_tr_gates<<<48, 256>>>(enc_wih0, ENC_WIH0_T, 4);
    k_tr_gates<<<48, 256>>>(enc_whh0, ENC_WHH0_T, 128);
    for (int l = 0; l < 3; l++) {
        k_tr_gates<<<48, 256>>>(enc_wih + l * 49152, ENC_WIH_T + l * 49152, 128);
        k_tr_gates<<<48, 256>>>(enc_whh + l * 49152, ENC_WHH_T + l * 49152, 128);
    }
    k_tr_gates<<<48, 256>>>(dec_wih0, DEC_WIH0_T, 4);
    k_tr_gates<<<48, 256>>>(dec_whh0, DEC_WHH0_T, 128);
    for (int l = 0; l < 3; l++) {
        k_tr_gates<<<48, 256>>>(dec_wih + l * 49152, DEC_WIH_T + l * 49152, 128);
        k_tr_gates<<<48, 256>>>(dec_whh + l * 49152, DEC_WHH_T + l * 49152, 128);
    }
    k_tr_lin1<<<48, 256>>>(lin1_w);

    gru_main<<<NBLOCKS, NTHREADS, smemBytes>>>(
        inp, tgt, enc_bih, enc_bhh, dec_bih, dec_bhh,
        lin1_b, lin2_w, lin2_b, out);
}

// round 4
// speedup vs baseline: 1.2175x; 1.1380x over previous
#include <cuda_runtime.h>
#include <math.h>

#define Hh 128
#define CB 32
#define PAD 36
#define HS_L (Hh*PAD)
#define NTHREADS 512
#define NBLOCKS 128

// Output layout (concatenated return tuple, float32):
// decoder_output (4096,100,4) | dec_hidden (4,4096,128) | encoder_output (4096,64,128) | enc_hidden (4,4096,128) | loss (1)
#define DEC_OUT_OFF 0ul
#define DEC_HID_OFF 1638400ul
#define ENC_OUT_OFF 3735552ul
#define ENC_HID_OFF 37289984ul
#define LOSS_OFF    39387136ul

// Packed weight scratch (floats).
// L0H: [k(128)][j(128)][4] = {whr,whz,whn,0}
// L0X: [k(4)][j(128)][4]   = {wxr,wxz,wxn,0}
// F:   [k(128)][j(128)][8] = {whr,whz,whn,wxr,wxz,wxn,0,0}
// LIN1:[k(128)][i(128)]
#define ENC_L0H 0
#define ENC_L0X 65536
#define DEC_L0H 67584
#define DEC_L0X 133120
#define ENC_F   135168
#define DEC_F   528384
#define LIN1_T  921600
#define WT_TOTAL 937984

__device__ float g_wt[WT_TOTAL];

// ---------------- packed f32x2 helpers ----------------

typedef unsigned long long u64;

__device__ __forceinline__ u64 pack2s(float v)
{
    u64 r;
    asm("mov.b64 %0,{%1,%1};" : "=l"(r) : "f"(v));
    return r;
}
__device__ __forceinline__ void unpack2(u64 v, float& lo, float& hi)
{
    asm("mov.b64 {%0,%1},%2;" : "=f"(lo), "=f"(hi) : "l"(v));
}
__device__ __forceinline__ void ffma2(u64& d, u64 a, u64 b)
{
    asm("fma.rn.f32x2 %0,%1,%2,%3;" : "=l"(d) : "l"(a), "l"(b), "l"(d));
}

// ---------------- prep kernels ----------------

// whh0 [3*128][128] -> L0-style h pack at dstOff
__global__ void k_pack_h0(const float* __restrict__ whh0, int dstOff)
{
    for (int idx = blockIdx.x * blockDim.x + threadIdx.x; idx < 128 * 128;
         idx += gridDim.x * blockDim.x) {
        int k = idx >> 7, j = idx & 127;
        float* d = g_wt + dstOff + idx * 4;
        d[0] = whh0[(0 * 128 + j) * 128 + k];
        d[1] = whh0[(1 * 128 + j) * 128 + k];
        d[2] = whh0[(2 * 128 + j) * 128 + k];
        d[3] = 0.0f;
    }
}

// wih0 [3*128][4] -> L0X pack at dstOff
__global__ void k_pack_x0(const float* __restrict__ wih0, int dstOff)
{
    for (int idx = blockIdx.x * blockDim.x + threadIdx.x; idx < 4 * 128;
         idx += gridDim.x * blockDim.x) {
        int k = idx >> 7, j = idx & 127;
        float* d = g_wt + dstOff + idx * 4;
        d[0] = wih0[(0 * 128 + j) * 4 + k];
        d[1] = wih0[(1 * 128 + j) * 4 + k];
        d[2] = wih0[(2 * 128 + j) * 4 + k];
        d[3] = 0.0f;
    }
}

// wih/whh [3*128][128] -> fused 8-float records at dstOff
__global__ void k_pack_fused(const float* __restrict__ wih,
                             const float* __restrict__ whh, int dstOff)
{
    for (int idx = blockIdx.x * blockDim.x + threadIdx.x; idx < 128 * 128;
         idx += gridDim.x * blockDim.x) {
        int k = idx >> 7, j = idx & 127;
        float* d = g_wt + dstOff + idx * 8;
        d[0] = whh[(0 * 128 + j) * 128 + k];
        d[1] = whh[(1 * 128 + j) * 128 + k];
        d[2] = whh[(2 * 128 + j) * 128 + k];
        d[3] = wih[(0 * 128 + j) * 128 + k];
        d[4] = wih[(1 * 128 + j) * 128 + k];
        d[5] = wih[(2 * 128 + j) * 128 + k];
        d[6] = 0.0f;
        d[7] = 0.0f;
    }
}

// lin1_w [H][H] -> g_wt[LIN1_T + k*H + i]
__global__ void k_tr_lin1(const float* __restrict__ src)
{
    for (int idx = blockIdx.x * blockDim.x + threadIdx.x; idx < Hh * Hh;
         idx += gridDim.x * blockDim.x) {
        int i = idx >> 7;
        int k = idx & (Hh - 1);
        g_wt[LIN1_T + k * Hh + i] = src[idx];
    }
}

__global__ void k_zero_loss(float* __restrict__ out)
{
    if (threadIdx.x == 0) out[LOSS_OFF] = 0.0f;
}

// ---------------- main kernel ----------------

__device__ __forceinline__ float sigf(float x)
{
    return 1.0f / (1.0f + __expf(-x));
}

__device__ __forceinline__ float tanhfast(float x)
{
    float t = __expf(2.0f * x);
    return 1.0f - 2.0f / (t + 1.0f);   // safe at +/- inf
}

// Pointwise GRU gate update for this thread's 8 batch elements.
__device__ __forceinline__ void gru_pointwise(
    u64* ar, u64* az, u64* ain, u64* ahn, float* hrow0)
{
#pragma unroll
    for (int p = 0; p < 4; p++) {
        float r0, r1, z0, z1, i0, i1, n0, n1;
        unpack2(ar[p], r0, r1);
        unpack2(az[p], z0, z1);
        unpack2(ain[p], i0, i1);
        unpack2(ahn[p], n0, n1);
        float h0 = hrow0[2 * p];
        float h1 = hrow0[2 * p + 1];
        float rr0 = sigf(r0), rr1 = sigf(r1);
        float zz0 = sigf(z0), zz1 = sigf(z1);
        float nn0 = tanhfast(fmaf(rr0, n0, i0));
        float nn1 = tanhfast(fmaf(rr1, n1, i1));
        hrow0[2 * p]     = fmaf(zz0, h0 - nn0, nn0);
        hrow0[2 * p + 1] = fmaf(zz1, h1 - nn1, nn1);
    }
}

// Fused GRU layer (input dim = 128, input activations xs = previous layer h).
__device__ __forceinline__ void gru_layer_f(
    const float* __restrict__ wf,
    const float* __restrict__ bih, const float* __restrict__ bhh,
    const float* __restrict__ xs, float* __restrict__ hsl,
    int j, int bB)
{
    u64 ar[4], az[4], ain[4], ahn[4];
    {
        u64 br  = pack2s(bih[j] + bhh[j]);
        u64 bz  = pack2s(bih[Hh + j] + bhh[Hh + j]);
        u64 bi  = pack2s(bih[2 * Hh + j]);
        u64 bh2 = pack2s(bhh[2 * Hh + j]);
#pragma unroll
        for (int p = 0; p < 4; p++) {
            ar[p] = br; az[p] = bz; ain[p] = bi; ahn[p] = bh2;
        }
    }
    const float* wb = wf + j * 8;
    float4 wa = *(const float4*)(wb);
    float2 wc = *(const float2*)(wb + 4);
#pragma unroll 4
    for (int k = 0; k < Hh; k++) {
        float4 wa_c = wa;
        float2 wc_c = wc;
        if (k < Hh - 1) {
            wa = *(const float4*)(wb + (k + 1) * 1024);
            wc = *(const float2*)(wb + (k + 1) * 1024 + 4);
        }
        u64 wr = pack2s(wa_c.x), wz = pack2s(wa_c.y), wn = pack2s(wa_c.z);
        u64 vr = pack2s(wa_c.w), vz = pack2s(wc_c.x), vn = pack2s(wc_c.y);
        const ulonglong2* hq = (const ulonglong2*)(hsl + k * PAD + bB);
        const ulonglong2* xq = (const ulonglong2*)(xs + k * PAD + bB);
        ulonglong2 ha = hq[0], hb = hq[1];
        ulonglong2 xa = xq[0], xb = xq[1];
        u64 hv[4] = {ha.x, ha.y, hb.x, hb.y};
        u64 xv[4] = {xa.x, xa.y, xb.x, xb.y};
#pragma unroll
        for (int p = 0; p < 4; p++) {
            ffma2(ar[p], hv[p], wr);
            ffma2(az[p], hv[p], wz);
            ffma2(ahn[p], hv[p], wn);
            ffma2(ar[p], xv[p], vr);
            ffma2(az[p], xv[p], vz);
            ffma2(ain[p], xv[p], vn);
        }
    }
    __syncthreads();   // all reads of hsl done before overwrite
    gru_pointwise(ar, az, ain, ahn, hsl + j * PAD + bB);
    __syncthreads();   // hsl ready for next layer
}

// Layer 0 (input dim 4 from x0s).
__device__ __forceinline__ void gru_layer_0(
    const float* __restrict__ wh0, const float* __restrict__ wx0,
    const float* __restrict__ bih, const float* __restrict__ bhh,
    const float* __restrict__ xs, float* __restrict__ hsl,
    int j, int bB)
{
    u64 ar[4], az[4], ain[4], ahn[4];
    {
        u64 br  = pack2s(bih[j] + bhh[j]);
        u64 bz  = pack2s(bih[Hh + j] + bhh[Hh + j]);
        u64 bi  = pack2s(bih[2 * Hh + j]);
        u64 bh2 = pack2s(bhh[2 * Hh + j]);
#pragma unroll
        for (int p = 0; p < 4; p++) {
            ar[p] = br; az[p] = bz; ain[p] = bi; ahn[p] = bh2;
        }
    }
    const float* wb = wh0 + j * 4;
    float4 wa = *(const float4*)(wb);
#pragma unroll 4
    for (int k = 0; k < Hh; k++) {
        float4 wa_c = wa;
        if (k < Hh - 1) wa = *(const float4*)(wb + (k + 1) * 512);
        u64 wr = pack2s(wa_c.x), wz = pack2s(wa_c.y), wn = pack2s(wa_c.z);
        const ulonglong2* hq = (const ulonglong2*)(hsl + k * PAD + bB);
        ulonglong2 ha = hq[0], hb = hq[1];
        u64 hv[4] = {ha.x, ha.y, hb.x, hb.y};
#pragma unroll
        for (int p = 0; p < 4; p++) {
            ffma2(ar[p], hv[p], wr);
            ffma2(az[p], hv[p], wz);
            ffma2(ahn[p], hv[p], wn);
        }
    }
    const float* xb = wx0 + j * 4;
#pragma unroll
    for (int k = 0; k < 4; k++) {
        float4 va = *(const float4*)(xb + k * 512);
        u64 vr = pack2s(va.x), vz = pack2s(va.y), vn = pack2s(va.z);
        const ulonglong2* xq = (const ulonglong2*)(xs + k * PAD + bB);
        ulonglong2 xa = xq[0], xb2 = xq[1];
        u64 xv[4] = {xa.x, xa.y, xb2.x, xb2.y};
#pragma unroll
        for (int p = 0; p < 4; p++) {
            ffma2(ar[p], xv[p], vr);
            ffma2(az[p], xv[p], vz);
            ffma2(ain[p], xv[p], vn);
        }
    }
    __syncthreads();
    gru_pointwise(ar, az, ain, ahn, hsl + j * PAD + bB);
    __syncthreads();
}

__global__ void __launch_bounds__(NTHREADS, 1) gru_main(
    const float* __restrict__ inp, const float* __restrict__ tgt,
    const float* __restrict__ enc_bih, const float* __restrict__ enc_bhh,
    const float* __restrict__ dec_bih, const float* __restrict__ dec_bhh,
    const float* __restrict__ lin1_b, const float* __restrict__ lin2_w,
    const float* __restrict__ lin2_b,
    float* __restrict__ out)
{
    extern __shared__ float sm[];
    float* hs  = sm;                        // [4][H][PAD]
    float* o1s = sm + 4 * HS_L;             // [H][PAD]
    float* x0s = o1s + HS_L;                // [4][PAD]
    float* red = x0s + 4 * PAD;             // [NTHREADS]

    const int tid  = threadIdx.x;
    const int lane = tid & 31;
    const int w    = tid >> 5;
    const int j    = ((w & 3) << 5) | lane;
    const int bB   = (w >> 2) << 3;         // 8 batch elements per thread
    const int b0   = blockIdx.x * CB;

    for (int u = tid; u < 4 * HS_L; u += NTHREADS) hs[u] = 0.0f;
    if (tid < CB * 4) {
        int b = tid >> 2, e = tid & 3;
        out[DEC_OUT_OFF + (size_t)(b0 + b) * 400 + e] =
            inp[(size_t)(b0 + b) * 256 + e];
    }
    __syncthreads();

    // ---------------- encoder: 64 steps ----------------
    for (int t = 0; t < 64; t++) {
        if (tid < CB * 4) {
            int b = tid >> 2, e = tid & 3;
            x0s[e * PAD + b] = inp[(size_t)(b0 + b) * 256 + t * 4 + e];
        }
        __syncthreads();
        gru_layer_0(g_wt + ENC_L0H, g_wt + ENC_L0X,
                    enc_bih, enc_bhh, x0s, hs, j, bB);
#pragma unroll 1
        for (int l = 1; l < 4; l++) {
            gru_layer_f(g_wt + ENC_F + (l - 1) * 131072,
                        enc_bih + l * 384, enc_bhh + l * 384,
                        hs + (l - 1) * HS_L, hs + l * HS_L, j, bB);
        }
        const float* h3 = hs + 3 * HS_L;
        for (int u = tid; u < CB * Hh; u += NTHREADS) {
            int b = u >> 7, k = u & 127;
            out[ENC_OUT_OFF + (size_t)(b0 + b) * 8192 + t * 128 + k] =
                h3[k * PAD + b];
        }
        // no barrier needed: next write to hs[3] / x0s is many barriers away
    }
    // enc_hidden (L,B,H)
    for (int u = tid; u < 4 * CB * Hh; u += NTHREADS) {
        int l = u >> 12, r = u & 4095, b = r >> 7, k = r & 127;
        out[ENC_HID_OFF + (size_t)l * 524288 + (size_t)(b0 + b) * 128 + k] =
            hs[l * HS_L + k * PAD + b];
    }

    // ---------------- decoder: 99 steps ----------------
    float lossAcc = 0.0f;
    for (int s = 0; s < 99; s++) {
        if (tid < CB * 4) {
            int b = tid >> 2, e = tid & 3;
            float xv = (s == 0) ? inp[(size_t)(b0 + b) * 256 + e]
                                : tgt[(size_t)(b0 + b) * 400 + s * 4 + e];
            x0s[e * PAD + b] = xv;
        }
        __syncthreads();
        gru_layer_0(g_wt + DEC_L0H, g_wt + DEC_L0X,
                    dec_bih, dec_bhh, x0s, hs, j, bB);
#pragma unroll 1
        for (int l = 1; l < 4; l++) {
            gru_layer_f(g_wt + DEC_F + (l - 1) * 131072,
                        dec_bih + l * 384, dec_bhh + l * 384,
                        hs + (l - 1) * HS_L, hs + l * HS_L, j, bB);
        }
        // lin1 + relu -> o1s
        {
            u64 acc[4];
            u64 bi = pack2s(lin1_b[j]);
#pragma unroll
            for (int p = 0; p < 4; p++) acc[p] = bi;
            const float* top = hs + 3 * HS_L;
            const float* wt1 = g_wt + LIN1_T + j;
            float wv_f = wt1[0];
#pragma unroll 4
            for (int k = 0; k < Hh; k++) {
                float wv_c = wv_f;
                if (k < Hh - 1) wv_f = wt1[(k + 1) * Hh];
                u64 wv = pack2s(wv_c);
                const ulonglong2* tq = (const ulonglong2*)(top + k * PAD + bB);
                ulonglong2 ta = tq[0], tb = tq[1];
                u64 tv[4] = {ta.x, ta.y, tb.x, tb.y};
#pragma unroll
                for (int p = 0; p < 4; p++)
                    ffma2(acc[p], tv[p], wv);
            }
            float* orow = o1s + j * PAD + bB;
#pragma unroll
            for (int p = 0; p < 4; p++) {
                float a0, a1;
                unpack2(acc[p], a0, a1);
                orow[2 * p]     = fmaxf(a0, 0.0f);
                orow[2 * p + 1] = fmaxf(a1, 0.0f);
            }
        }
        __syncthreads();
        // lin2 + loss + store
        if (tid < CB * 4) {
            int b = tid >> 2, e = tid & 3;
            float acc = lin2_b[e];
#pragma unroll 4
            for (int i = 0; i < Hh; i++)
                acc = fmaf(o1s[i * PAD + b], lin2_w[e * Hh + i], acc);
            float y = tgt[(size_t)(b0 + b) * 400 + (s + 1) * 4 + e];
            float d = acc - y;
            lossAcc += d * d;
            out[DEC_OUT_OFF + (size_t)(b0 + b) * 400 + (s + 1) * 4 + e] = acc;
        }
        __syncthreads();   // o1s reads done before next step's lin1 writes
    }
    // dec_hidden (L,B,H)
    for (int u = tid; u < 4 * CB * Hh; u += NTHREADS) {
        int l = u >> 12, r = u & 4095, b = r >> 7, k = r & 127;
        out[DEC_HID_OFF + (size_t)l * 524288 + (size_t)(b0 + b) * 128 + k] =
            hs[l * HS_L + k * PAD + b];
    }

    // loss reduction
    red[tid] = lossAcc;
    __syncthreads();
    for (int s2 = NTHREADS / 2; s2 > 0; s2 >>= 1) {
        if (tid < s2) red[tid] += red[tid + s2];
        __syncthreads();
    }
    if (tid == 0) atomicAdd(out + LOSS_OFF, red[0] * (1.0f / 16384.0f));
}

// ---------------- launch ----------------

extern "C" void kernel_launch(void* const* d_in, const int* in_sizes, int n_in,
                              void* d_out, int out_size)
{
    const float* inp      = (const float*)d_in[0];
    const float* tgt      = (const float*)d_in[1];
    const float* enc_wih0 = (const float*)d_in[2];
    const float* enc_whh0 = (const float*)d_in[3];
    const float* enc_wih  = (const float*)d_in[4];
    const float* enc_whh  = (const float*)d_in[5];
    const float* enc_bih  = (const float*)d_in[6];
    const float* enc_bhh  = (const float*)d_in[7];
    const float* dec_wih0 = (const float*)d_in[8];
    const float* dec_whh0 = (const float*)d_in[9];
    const float* dec_wih  = (const float*)d_in[10];
    const float* dec_whh  = (const float*)d_in[11];
    const float* dec_bih  = (const float*)d_in[12];
    const float* dec_bhh  = (const float*)d_in[13];
    const float* lin1_w   = (const float*)d_in[14];
    const float* lin1_b   = (const float*)d_in[15];
    const float* lin2_w   = (const float*)d_in[16];
    const float* lin2_b   = (const float*)d_in[17];
    float* out = (float*)d_out;

    const int smemBytes = (4 * HS_L + HS_L + 4 * PAD + NTHREADS) * 4;
    cudaFuncSetAttribute(gru_main, cudaFuncAttributeMaxDynamicSharedMemorySize,
                         smemBytes);

    k_zero_loss<<<1, 32>>>(out);

    k_pack_h0<<<32, 512>>>(enc_whh0, ENC_L0H);
    k_pack_x0<<<1, 512>>>(enc_wih0, ENC_L0X);
    k_pack_h0<<<32, 512>>>(dec_whh0, DEC_L0H);
    k_pack_x0<<<1, 512>>>(dec_wih0, DEC_L0X);
    for (int l = 0; l < 3; l++) {
        k_pack_fused<<<32, 512>>>(enc_wih + l * 49152, enc_whh + l * 49152,
                                  ENC_F + l * 131072);
        k_pack_fused<<<32, 512>>>(dec_wih + l * 49152, dec_whh + l * 49152,
                                  DEC_F + l * 131072);
    }
    k_tr_lin1<<<32, 512>>>(lin1_w);

    gru_main<<<NBLOCKS, NTHREADS, smemBytes>>>(
        inp, tgt, enc_bih, enc_bhh, dec_bih, dec_bhh,
        lin1_b, lin2_w, lin2_b, out);
}